// round 2
// baseline (speedup 1.0000x reference)
#include <cuda_runtime.h>
#include <math.h>

// Problem constants
#define HH 256
#define WW 256
#define HWSZ 65536   // 256*256

// ---------------- scratch (device globals; no runtime allocation) -------------
__device__ float g_xp[2 * HWSZ];          // preprocess output (B,1,H,W)
__device__ float g_t [2 * 192 * HWSZ];    // branch-concat buffer (B,192,H,W)
__device__ float g_h [2 * 64 * HWSZ];     // after w_p1 (B,64,H,W)
__device__ float g_m [2 * 64 * HWSZ];     // after wbp / BN-relu (B,64,H,W)
__device__ float g_sum[64];
__device__ float g_var[64];
__device__ float g_ysum[2 * 64];
__device__ float g_y [2 * 64];

// ---------------- packed fp32x2 helpers (sm_100+ PTX) ----------------
__device__ __forceinline__ unsigned long long pack2(float lo, float hi) {
    unsigned long long r;
    asm("mov.b64 %0, {%1, %2};" : "=l"(r) : "f"(lo), "f"(hi));
    return r;
}
__device__ __forceinline__ void unpack2(unsigned long long v, float& lo, float& hi) {
    asm("mov.b64 {%0, %1}, %2;" : "=f"(lo), "=f"(hi) : "l"(v));
}
__device__ __forceinline__ void ffma2(unsigned long long& acc, unsigned long long a,
                                      unsigned long long b) {
    asm("fma.rn.f32x2 %0, %1, %2, %0;" : "+l"(acc) : "l"(a), "l"(b));
}

// ---------------- helpers ----------------
__device__ __forceinline__ float blendv(const float* __restrict__ x, int b, int i, int j) {
    // reflect (no edge repeat), then gamma blend
    i = (i < 0) ? -i : ((i >= HH) ? 2 * HH - 2 - i : i);
    j = (j < 0) ? -j : ((j >= WW) ? 2 * WW - 2 - j : j);
    float v = x[(b << 16) + (i << 8) + j];
    float g = fminf(fmaxf((v + 1.0f) * 0.5f, 1e-6f), 1.0f);
    return 0.6f * g + 0.4f * g * sqrtf(g);   // (1-a)*g + a*g^1.5
}

__device__ __forceinline__ float block_sum256(float v) {
    __shared__ float red[32];
    int lane = threadIdx.x & 31;
    int wid  = threadIdx.x >> 5;
    #pragma unroll
    for (int o = 16; o > 0; o >>= 1) v += __shfl_down_sync(0xffffffffu, v, o);
    if (lane == 0) red[wid] = v;
    __syncthreads();
    float r = 0.0f;
    if (wid == 0) {
        r = (lane < 8) ? red[lane] : 0.0f;
        #pragma unroll
        for (int o = 4; o > 0; o >>= 1) r += __shfl_down_sync(0xffffffffu, r, o);
    }
    __syncthreads();
    return r;  // valid in thread 0
}

// ---------------- 1) bilateral preprocess ----------------
__global__ void preprocess_kernel(const float* __restrict__ x) {
    int gid = blockIdx.x * 256 + threadIdx.x;   // 0 .. 2*HW-1
    int b = gid >> 16;
    int p = gid & 65535;
    int i = p >> 8, j = p & 255;
    float c = blendv(x, b, i, j);
    float num = 0.0f, den = 0.0f;
    #pragma unroll
    for (int di = -2; di <= 2; di++) {
        #pragma unroll
        for (int dj = -2; dj <= 2; dj++) {
            if (di * di + dj * dj > 4) continue;
            float sh = blendv(x, b, i + di, j + dj);
            float sw = expf(-0.5f * (float)(di * di + dj * dj) / 2500.0f);
            float d = sh - c;
            float wgt = sw * expf(-200.0f * d * d);   // -0.5/0.05^2 = -200
            num += wgt * sh;
            den += wgt;
        }
    }
    g_xp[gid] = num / den;
}

// ---------------- 2) stage-1 branch convs (1ch -> 192ch) + relu ----------------
// weights in smem transposed to [tap][oc] so oc-pairs are contiguous (packed LDS)
__global__ __launch_bounds__(256) void stage1_kernel(
    const float* __restrict__ w3, const float* __restrict__ w5, const float* __restrict__ w7) {
    __shared__ float sp[22 * 22];
    __shared__ __align__(16) float sw[5312];   // 576 + 1600 + 3136
    int tx = threadIdx.x, ty = threadIdx.y, tid = ty * 16 + tx;
    int b  = blockIdx.z;
    int bx = blockIdx.x * 16, by = blockIdx.y * 16;

    for (int i = tid; i < 576;  i += 256) { int t = i >> 6, oc = i & 63; sw[i]        = w3[oc * 9  + t]; }
    for (int i = tid; i < 1600; i += 256) { int t = i >> 6, oc = i & 63; sw[576 + i]  = w5[oc * 25 + t]; }
    for (int i = tid; i < 3136; i += 256) { int t = i >> 6, oc = i & 63; sw[2176 + i] = w7[oc * 49 + t]; }
    for (int i = tid; i < 484; i += 256) {   // (16+6)^2 patch, pad 3, zero-fill
        int py = i / 22, px = i % 22;
        int gy = by + py - 3, gx = bx + px - 3;
        float v = 0.0f;
        if (gy >= 0 && gy < HH && gx >= 0 && gx < WW) v = g_xp[(b << 16) + (gy << 8) + gx];
        sp[i] = v;
    }
    __syncthreads();

    int gy = by + ty, gx = bx + tx;
    int obase = ((b * 192) << 16) + (gy << 8) + gx;

    // 3x3 branch (patch center offset +2)
    {
        unsigned long long acc[32];
        #pragma unroll
        for (int q = 0; q < 32; q++) acc[q] = 0ull;
        #pragma unroll
        for (int t = 0; t < 9; t++) {
            int ky = t / 3, kx = t % 3;
            float v = sp[(ty + 2 + ky) * 22 + tx + 2 + kx];
            unsigned long long vv = pack2(v, v);
            const ulonglong2* wr = (const ulonglong2*)(sw + t * 64);
            #pragma unroll
            for (int q = 0; q < 16; q++) {
                ulonglong2 w2 = wr[q];
                ffma2(acc[2 * q],     w2.x, vv);
                ffma2(acc[2 * q + 1], w2.y, vv);
            }
        }
        #pragma unroll
        for (int q = 0; q < 32; q++) {
            float lo, hi; unpack2(acc[q], lo, hi);
            g_t[obase + ((2 * q)     << 16)] = fmaxf(lo, 0.0f);
            g_t[obase + ((2 * q + 1) << 16)] = fmaxf(hi, 0.0f);
        }
    }
    // 5x5 branch (offset +1)
    {
        unsigned long long acc[32];
        #pragma unroll
        for (int q = 0; q < 32; q++) acc[q] = 0ull;
        #pragma unroll
        for (int t = 0; t < 25; t++) {
            int ky = t / 5, kx = t % 5;
            float v = sp[(ty + 1 + ky) * 22 + tx + 1 + kx];
            unsigned long long vv = pack2(v, v);
            const ulonglong2* wr = (const ulonglong2*)(sw + 576 + t * 64);
            #pragma unroll
            for (int q = 0; q < 16; q++) {
                ulonglong2 w2 = wr[q];
                ffma2(acc[2 * q],     w2.x, vv);
                ffma2(acc[2 * q + 1], w2.y, vv);
            }
        }
        #pragma unroll
        for (int q = 0; q < 32; q++) {
            float lo, hi; unpack2(acc[q], lo, hi);
            g_t[obase + ((64 + 2 * q)     << 16)] = fmaxf(lo, 0.0f);
            g_t[obase + ((64 + 2 * q + 1) << 16)] = fmaxf(hi, 0.0f);
        }
    }
    // 7x7 branch (offset 0)
    {
        unsigned long long acc[32];
        #pragma unroll
        for (int q = 0; q < 32; q++) acc[q] = 0ull;
        for (int t = 0; t < 49; t++) {
            int ky = t / 7, kx = t % 7;
            float v = sp[(ty + ky) * 22 + tx + kx];
            unsigned long long vv = pack2(v, v);
            const ulonglong2* wr = (const ulonglong2*)(sw + 2176 + t * 64);
            #pragma unroll
            for (int q = 0; q < 16; q++) {
                ulonglong2 w2 = wr[q];
                ffma2(acc[2 * q],     w2.x, vv);
                ffma2(acc[2 * q + 1], w2.y, vv);
            }
        }
        #pragma unroll
        for (int q = 0; q < 32; q++) {
            float lo, hi; unpack2(acc[q], lo, hi);
            g_t[obase + ((128 + 2 * q)     << 16)] = fmaxf(lo, 0.0f);
            g_t[obase + ((128 + 2 * q + 1) << 16)] = fmaxf(hi, 0.0f);
        }
    }
}

// ---------------- 3) pointwise 192 -> 64 (used for w_p1 and wbp) ----------------
// phase 0: g_t -> g_h ; phase 1: g_t -> g_m
__global__ __launch_bounds__(256) void pw_kernel(const float* __restrict__ w, int phase) {
    __shared__ __align__(16) float ws[12288];   // transposed: ws[c*64 + oc] = w[oc*192 + c]
    int tid = threadIdx.x;
    for (int i = tid; i < 12288; i += 256) ws[i] = w[(i & 63) * 192 + (i >> 6)];
    __syncthreads();

    float* out = (phase == 0) ? g_h : g_m;
    int gid = blockIdx.x * 256 + tid;          // 0 .. 2*HW-1
    int b = gid >> 16, pix = gid & 65535;
    const float* ip = g_t + ((b * 192) << 16) + pix;

    unsigned long long acc[32];
    #pragma unroll
    for (int q = 0; q < 32; q++) acc[q] = 0ull;

    float nxt = ip[0];
    for (int c = 0; c < 192; c++) {
        float tv = nxt;
        if (c < 191) nxt = ip[(c + 1) << 16];
        unsigned long long vv = pack2(tv, tv);
        const ulonglong2* wr = (const ulonglong2*)(ws + c * 64);
        #pragma unroll
        for (int q = 0; q < 16; q++) {
            ulonglong2 w2 = wr[q];
            ffma2(acc[2 * q],     w2.x, vv);
            ffma2(acc[2 * q + 1], w2.y, vv);
        }
    }
    float* op = out + ((b * 64) << 16) + pix;
    #pragma unroll
    for (int q = 0; q < 32; q++) {
        float lo, hi; unpack2(acc[q], lo, hi);
        op[(2 * q)     << 16] = lo;
        op[(2 * q + 1) << 16] = hi;
    }
}

// ---------------- 4) stage-2 branch convs (64 -> 64ch per branch) + relu -------
// block (32,8): 32x32 pixel tile, each thread 4 pixels x 8 output channels.
// weights in smem as [tap][8 oc] so oc-pairs load pre-packed via LDS.128.
template <int K>
__global__ __launch_bounds__(256) void stage2_kernel(const float* __restrict__ w, int oc_base) {
    constexpr int P = K / 2, TAPS = K * K;
    constexpr int PW = 32 + 2 * P;
    __shared__ float sp[PW * PW];
    __shared__ __align__(16) float sw[TAPS * 8];
    int tx = threadIdx.x, ty = threadIdx.y;
    int tid = ty * 32 + tx;
    int bx = blockIdx.x * 32, by = blockIdx.y * 32;
    int zz = blockIdx.z;                 // b*8 + och-group
    int b = zz >> 3, og = zz & 7;

    unsigned long long acc[4][4];        // 4 pixels x 4 oc-pairs
    #pragma unroll
    for (int k = 0; k < 4; k++)
        #pragma unroll
        for (int p = 0; p < 4; p++) acc[k][p] = 0ull;

    for (int ic = 0; ic < 64; ic++) {
        const float* ip = g_h + ((b * 64 + ic) << 16);
        for (int i = tid; i < PW * PW; i += 256) {
            int py = i / PW, px = i % PW;
            int gy = by + py - P, gx = bx + px - P;
            float v = 0.0f;
            if (gy >= 0 && gy < HH && gx >= 0 && gx < WW) v = ip[(gy << 8) + gx];
            sp[i] = v;
        }
        for (int i = tid; i < 8 * TAPS; i += 256) {
            int t = i >> 3, o = i & 7;
            sw[i] = w[((og * 8 + o) * 64 + ic) * TAPS + t];
        }
        __syncthreads();

        for (int ky = 0; ky < K; ky++) {
            #pragma unroll
            for (int kx = 0; kx < K; kx++) {
                int t = ky * K + kx;
                ulonglong2 wa = *(const ulonglong2*)(sw + t * 8);
                ulonglong2 wb = *(const ulonglong2*)(sw + t * 8 + 4);
                #pragma unroll
                for (int k = 0; k < 4; k++) {
                    float v = sp[(ty + 8 * k + ky) * PW + tx + kx];
                    unsigned long long vv = pack2(v, v);
                    ffma2(acc[k][0], wa.x, vv);
                    ffma2(acc[k][1], wa.y, vv);
                    ffma2(acc[k][2], wb.x, vv);
                    ffma2(acc[k][3], wb.y, vv);
                }
            }
        }
        __syncthreads();
    }

    #pragma unroll
    for (int k = 0; k < 4; k++) {
        int gy = by + ty + 8 * k;
        #pragma unroll
        for (int p = 0; p < 4; p++) {
            float lo, hi; unpack2(acc[k][p], lo, hi);
            int oc = oc_base + og * 8 + 2 * p;
            g_t[((b * 192 + oc)     << 16) + (gy << 8) + bx + tx] = fmaxf(lo, 0.0f);
            g_t[((b * 192 + oc + 1) << 16) + (gy << 8) + bx + tx] = fmaxf(hi, 0.0f);
        }
    }
}

// ---------------- 5) batchnorm statistics + BN-relu + SE ----------------
__global__ void zero_stats_kernel() {
    int t = threadIdx.x;
    if (t < 64)  { g_sum[t] = 0.0f; g_var[t] = 0.0f; }
    if (t < 128) { g_ysum[t] = 0.0f; }
}

__global__ void chan_sum_kernel() {            // grid (32, 64)
    int c = blockIdx.y;
    int base = blockIdx.x * 4096;
    float s = 0.0f;
    for (int i = threadIdx.x; i < 4096; i += 256) {
        int e = base + i;
        int b = e >> 16, p = e & 65535;
        s += g_m[((b * 64 + c) << 16) + p];
    }
    s = block_sum256(s);
    if (threadIdx.x == 0) atomicAdd(&g_sum[c], s);
}

__global__ void chan_var_kernel() {            // grid (32, 64)
    int c = blockIdx.y;
    float mean = g_sum[c] * (1.0f / 131072.0f);
    int base = blockIdx.x * 4096;
    float s = 0.0f;
    for (int i = threadIdx.x; i < 4096; i += 256) {
        int e = base + i;
        int b = e >> 16, p = e & 65535;
        float d = g_m[((b * 64 + c) << 16) + p] - mean;
        s += d * d;
    }
    s = block_sum256(s);
    if (threadIdx.x == 0) atomicAdd(&g_var[c], s);
}

__global__ void bnrelu_kernel(const float* __restrict__ bn_g, const float* __restrict__ bn_b) {
    // grid (16, 64, 2)
    int c = blockIdx.y, b = blockIdx.z;
    float mean = g_sum[c] * (1.0f / 131072.0f);
    float var  = g_var[c] * (1.0f / 131072.0f);
    float sc = bn_g[c] * rsqrtf(var + 1e-5f);
    float sh = bn_b[c] - mean * sc;
    int base = ((b * 64 + c) << 16) + blockIdx.x * 4096;
    float s = 0.0f;
    for (int i = threadIdx.x; i < 4096; i += 256) {
        float v = g_m[base + i];
        float r = fmaxf(v * sc + sh, 0.0f);
        g_m[base + i] = r;
        s += r;
    }
    s = block_sum256(s);
    if (threadIdx.x == 0) atomicAdd(&g_ysum[b * 64 + c], s);
}

__global__ void se_kernel(const float* __restrict__ se1, const float* __restrict__ se2) {
    // <<<1,128>>>
    __shared__ float ys[128];
    __shared__ float z[8];
    int t = threadIdx.x;
    ys[t] = g_ysum[t] * (1.0f / 65536.0f);   // mean over H*W
    __syncthreads();
    if (t < 8) {
        int b = t >> 2, j = t & 3;
        float a = 0.0f;
        for (int c = 0; c < 64; c++) a += ys[b * 64 + c] * se1[j * 64 + c];
        z[t] = fmaxf(a, 0.0f);
    }
    __syncthreads();
    int b = t >> 6, c = t & 63;
    float a = 0.0f;
    #pragma unroll
    for (int j = 0; j < 4; j++) a += z[b * 4 + j] * se2[c * 4 + j];
    g_y[t] = 1.0f / (1.0f + expf(-a));
}

// ---------------- 6) final conv + residual: out = xp - conv(m*y, wf) ----------
__global__ void final_kernel(const float* __restrict__ wf, float* __restrict__ out) {
    __shared__ float wf2[576];
    __shared__ float sp[18 * 18];
    int tx = threadIdx.x, ty = threadIdx.y, tid = ty * 16 + tx;
    int b = blockIdx.z;
    int bx = blockIdx.x * 16, by = blockIdx.y * 16;
    for (int i = tid; i < 576; i += 256) wf2[i] = wf[i] * g_y[b * 64 + i / 9];

    float acc = 0.0f;
    for (int c = 0; c < 64; c++) {
        __syncthreads();
        const float* ip = g_m + ((b * 64 + c) << 16);
        for (int i = tid; i < 324; i += 256) {
            int py = i / 18, px = i % 18;
            int gy = by + py - 1, gx = bx + px - 1;
            float v = 0.0f;
            if (gy >= 0 && gy < HH && gx >= 0 && gx < WW) v = ip[(gy << 8) + gx];
            sp[i] = v;
        }
        __syncthreads();
        #pragma unroll
        for (int ky = 0; ky < 3; ky++)
            #pragma unroll
            for (int kx = 0; kx < 3; kx++)
                acc += sp[(ty + ky) * 18 + tx + kx] * wf2[c * 9 + ky * 3 + kx];
    }
    int gy = by + ty, gx = bx + tx;
    int o = (b << 16) + (gy << 8) + gx;
    out[o] = g_xp[o] - acc;
}

// ---------------- launch ----------------
extern "C" void kernel_launch(void* const* d_in, const int* in_sizes, int n_in,
                              void* d_out, int out_size) {
    const float* x    = (const float*)d_in[0];
    const float* w_i3 = (const float*)d_in[1];
    const float* w_i5 = (const float*)d_in[2];
    const float* w_i7 = (const float*)d_in[3];
    const float* w_p1 = (const float*)d_in[4];
    const float* wb3  = (const float*)d_in[5];
    const float* wb5  = (const float*)d_in[6];
    const float* wb7  = (const float*)d_in[7];
    const float* wbp  = (const float*)d_in[8];
    const float* bn_g = (const float*)d_in[9];
    const float* bn_b = (const float*)d_in[10];
    const float* se1  = (const float*)d_in[11];
    const float* se2  = (const float*)d_in[12];
    const float* wf   = (const float*)d_in[13];
    float* out = (float*)d_out;

    zero_stats_kernel<<<1, 256>>>();
    preprocess_kernel<<<512, 256>>>(x);
    stage1_kernel<<<dim3(16, 16, 2), dim3(16, 16)>>>(w_i3, w_i5, w_i7);
    pw_kernel<<<512, 256>>>(w_p1, 0);                               // g_t -> g_h
    stage2_kernel<3><<<dim3(8, 8, 16), dim3(32, 8)>>>(wb3, 0);      // g_h -> g_t[0:64]
    stage2_kernel<5><<<dim3(8, 8, 16), dim3(32, 8)>>>(wb5, 64);     // g_h -> g_t[64:128]
    stage2_kernel<7><<<dim3(8, 8, 16), dim3(32, 8)>>>(wb7, 128);    // g_h -> g_t[128:192]
    pw_kernel<<<512, 256>>>(wbp, 1);                                // g_t -> g_m
    chan_sum_kernel<<<dim3(32, 64), 256>>>();
    chan_var_kernel<<<dim3(32, 64), 256>>>();
    bnrelu_kernel<<<dim3(16, 64, 2), 256>>>(bn_g, bn_b);
    se_kernel<<<1, 128>>>(se1, se2);
    final_kernel<<<dim3(16, 16, 2), dim3(16, 16)>>>(wf, out);
}